// round 16
// baseline (speedup 1.0000x reference)
#include <cuda_runtime.h>
#include <cuda_fp16.h>
#include <math.h>
#include <stdint.h>

#define BB 16
#define SS 8192
#define HH 512
#define NROWS (BB*SS)

// ---------------------------------------------------------------------------
// helpers
// ---------------------------------------------------------------------------
__device__ __forceinline__ uint32_t smem_u32(const void* p) {
    uint32_t a;
    asm("{ .reg .u64 t; cvta.to.shared.u64 t, %1; cvt.u32.u64 %0, t; }" : "=r"(a) : "l"(p));
    return a;
}
#define SW128(o) ((o) ^ (((o) >> 3) & 0x70))

#define LDSM4(r0,r1,r2,r3,addr)                                               \
    asm volatile("ldmatrix.sync.aligned.m8n8.x4.shared.b16 {%0,%1,%2,%3}, [%4];" \
        : "=r"(r0),"=r"(r1),"=r"(r2),"=r"(r3) : "r"(addr))

#define CP_ASYNC16(dst, src)                                                  \
    asm volatile("cp.async.ca.shared.global [%0], [%1], 16;" :: "r"(dst), "l"(src) : "memory")
#define CP_COMMIT()  asm volatile("cp.async.commit_group;" ::: "memory")
#define CP_WAIT1()   asm volatile("cp.async.wait_group 1;" ::: "memory")

__device__ __forceinline__ void mma16816(float* c, const uint32_t* a,
                                         uint32_t b0, uint32_t b1) {
    asm volatile(
        "mma.sync.aligned.m16n8k16.row.col.f32.f16.f16.f32 "
        "{%0,%1,%2,%3}, {%4,%5,%6,%7}, {%8,%9}, {%0,%1,%2,%3};"
        : "+f"(c[0]), "+f"(c[1]), "+f"(c[2]), "+f"(c[3])
        : "r"(a[0]), "r"(a[1]), "r"(a[2]), "r"(a[3]), "r"(b0), "r"(b1));
}

__device__ __forceinline__ float fast_tanh(float x) {
    float xc = fminf(x, 30.f);
    float e  = __expf(2.f * xc);
    return __fdividef(e - 1.f, e + 1.f);
}

// ---------------------------------------------------------------------------
// scratch
// ---------------------------------------------------------------------------
__device__ float  g_qproj[BB*HH];
__device__ float  g_scores[BB*SS];
__device__ float2 g_pms[NROWS/128];   // per-scores-CTA (max, sumexp)
__device__ float  g_ctx_part[BB*64*HH];
__device__ __align__(16) __half g_Wh16[HH*HH];              // W_h fp16, [o][k]
__device__ __align__(16) __half g_enc16[(size_t)NROWS*HH];  // enc fp16, [m][k]

// smem layout (bytes): 3-stage ring, each stage = A 16KB + B 16KB
#define SM_A     0                      // 3 stages x 128 rows x 128B = 48KB
#define SM_B     49152                  // 3 stages x 128 rows x 128B = 48KB
#define SM_Q     98304                  // 128 floats
#define SM_V     98816                  // 128 floats
#define SM_PART  99328                  // 4 x 128 floats
#define SM_TOTAL 101376

// ---------------------------------------------------------------------------
// prep: whcast (blocks 0..255) + qproj (blocks 256..383)
// ---------------------------------------------------------------------------
__global__ __launch_bounds__(256)
void prep_kernel(const float* __restrict__ Wh,
                 const float* __restrict__ query,
                 const float* __restrict__ Wq) {
    const int bid = blockIdx.x;
    const int tid = threadIdx.x;
    if (bid < 256) {
        int i0 = (bid * 256 + tid) * 4;
        float4 x = *(const float4*)(Wh + i0);
        __half2 h01 = __float22half2_rn(make_float2(x.x, x.y));
        __half2 h23 = __float22half2_rn(make_float2(x.z, x.w));
        *(uint2*)(g_Wh16 + i0) = make_uint2(*(uint32_t*)&h01, *(uint32_t*)&h23);
    } else {
        const int bq = bid - 256;
        const int b  = bq >> 3;
        const int og = bq & 7;
        __shared__ float qs[HH];
        qs[tid] = query[b*HH + tid];
        qs[tid + 256] = query[b*HH + tid + 256];
        __syncthreads();

        const int o = og*64 + (tid >> 2);
        const int l = tid & 3;
        const float4* w4 = (const float4*)(Wq + (size_t)o*HH);
        const float4* q4 = (const float4*)qs;
        float acc = 0.f;
#pragma unroll 8
        for (int i = 0; i < 32; i++) {
            int k4 = l + 4*i;
            float4 w = w4[k4];
            float4 q = q4[k4];
            acc += w.x*q.x + w.y*q.y + w.z*q.z + w.w*q.w;
        }
        acc += __shfl_xor_sync(~0u, acc, 1);
        acc += __shfl_xor_sync(~0u, acc, 2);
        if (l == 0) g_qproj[b*HH + o] = acc;
    }
}

// ---------------------------------------------------------------------------
// convert one 64-k slice of A (128 rows) fp32 -> fp16: into swizzled smem slot
// AND to g_enc16 (for nc>=1 reuse and ctx). Same layout as the A cp.async.
// ---------------------------------------------------------------------------
__device__ __forceinline__ void conv_slice(char* smem, uint32_t slotBase,
                                           const float4* esrc, uint4* edst,
                                           int kn, int tid) {
#pragma unroll
    for (int i = 0; i < 4; i++) {
        int f = tid + i*256;
        int m = f >> 3, j = f & 7;
        const float4* s = esrc + (size_t)m*128 + kn*16 + j*2;
        float4 x0 = s[0];
        float4 x1 = s[1];
        __half2 a = __float22half2_rn(make_float2(x0.x, x0.y));
        __half2 b = __float22half2_rn(make_float2(x0.z, x0.w));
        __half2 c = __float22half2_rn(make_float2(x1.x, x1.y));
        __half2 d = __float22half2_rn(make_float2(x1.z, x1.w));
        uint4 o;
        o.x = *(uint32_t*)&a; o.y = *(uint32_t*)&b;
        o.z = *(uint32_t*)&c; o.w = *(uint32_t*)&d;
        *(uint4*)(smem + slotBase + SW128((uint32_t)(m*128 + j*16))) = o;
        edst[(size_t)m*64 + kn*8 + j] = o;
    }
}

// ---------------------------------------------------------------------------
// scores, single-pass fp16 mma, fully-async 3-stage pipeline (proven).
// Tail: ONE WARP computes this CTA's softmax partial (max, sumexp) -> g_pms.
// ---------------------------------------------------------------------------
__global__ __launch_bounds__(256, 2)
void scores_mma_kernel(const float* __restrict__ encf,
                       const float* __restrict__ v) {
    extern __shared__ char smem[];
    const uint32_t sb = smem_u32(smem);
    const int tid  = threadIdx.x;
    const int lane = tid & 31;
    const int wid  = tid >> 5;
    const int wm   = wid & 1;          // 0..1  (64 rows each)
    const int wn   = wid >> 1;         // 0..3  (32 cols each)
    const int m0   = blockIdx.x * 128;
    const int b    = m0 / SS;

    float* qs   = (float*)(smem + SM_Q);
    float* vs   = (float*)(smem + SM_V);
    float* part = (float*)(smem + SM_PART);   // [4][128]

    const uint32_t aRow = (uint32_t)(wm*64 + (lane & 15)) * 128u;
    const uint32_t aCol = ((lane >> 4) & 1) * 16u;
    const uint32_t bRow = (uint32_t)(wn*32 + (lane & 7) + ((lane & 16) ? 8 : 0)) * 128u;
    const uint32_t bCol = ((lane & 8) ? 16u : 0u);

    const float4* esrc = (const float4*)(encf + (size_t)m0*HH);   // fp32 A
    uint4*        edst = (uint4*)(g_enc16 + (size_t)m0*HH);       // fp16 A out
    const uint4*  asrc = (const uint4*)(g_enc16 + (size_t)m0*HH); // fp16 A in
    const uint4*  wsrc = (const uint4*)g_Wh16;

    float rowsc[8];
#pragma unroll
    for (int i = 0; i < 8; i++) rowsc[i] = 0.f;

    for (int nc = 0; nc < 4; nc++) {
        if (tid < 128) {
            qs[tid] = g_qproj[b*HH + nc*128 + tid];
            vs[tid] = v[nc*128 + tid];
        }

        float c[4][4][4];
#pragma unroll
        for (int mf = 0; mf < 4; mf++)
#pragma unroll
            for (int nf = 0; nf < 4; nf++)
#pragma unroll
                for (int e = 0; e < 4; e++) c[mf][nf][e] = 0.f;

        // ---- prologue: stages for kc=0,1
#pragma unroll
        for (int pk = 0; pk < 2; pk++) {
            if (nc == 0) {
                conv_slice(smem, SM_A + (uint32_t)pk*16384u, esrc, edst, pk, tid);
            } else {
#pragma unroll
                for (int i = 0; i < 4; i++) {     // A stage pk via cp.async
                    int f = tid + i*256;
                    int m = f >> 3, j = f & 7;
                    uint32_t dst = sb + SM_A + (uint32_t)pk*16384u +
                                   SW128((uint32_t)(m*128 + j*16));
                    CP_ASYNC16(dst, asrc + (size_t)m*(HH/8) + pk*8 + j);
                }
            }
#pragma unroll
            for (int i = 0; i < 4; i++) {         // B stage pk
                int f = tid + i*256;
                int n = f >> 3, j = f & 7;
                uint32_t dst = sb + SM_B + (uint32_t)pk*16384u +
                               SW128((uint32_t)(n*128 + j*16));
                CP_ASYNC16(dst, wsrc + (size_t)(nc*128 + n)*(HH/8) + pk*8 + j);
            }
            CP_COMMIT();
        }
        if (nc == 0) __syncthreads();   // prologue STS visible before LDSM

        for (int kc = 0; kc < 8; kc++) {
            CP_WAIT1();
            __syncthreads();

            if (kc < 6) {
                const int kn = kc + 2;
                const uint32_t slot = (uint32_t)(kn % 3);
                if (nc == 0) {
                    conv_slice(smem, SM_A + slot*16384u, esrc, edst, kn, tid);
                } else {
#pragma unroll
                    for (int i = 0; i < 4; i++) {
                        int f = tid + i*256;
                        int m = f >> 3, j = f & 7;
                        uint32_t dst = sb + SM_A + slot*16384u +
                                       SW128((uint32_t)(m*128 + j*16));
                        CP_ASYNC16(dst, asrc + (size_t)m*(HH/8) + kn*8 + j);
                    }
                }
#pragma unroll
                for (int i = 0; i < 4; i++) {
                    int f = tid + i*256;
                    int n = f >> 3, j = f & 7;
                    uint32_t dst = sb + SM_B + slot*16384u +
                                   SW128((uint32_t)(n*128 + j*16));
                    CP_ASYNC16(dst, wsrc + (size_t)(nc*128 + n)*(HH/8) + kn*8 + j);
                }
            }
            CP_COMMIT();

            const uint32_t aBase = sb + SM_A + (uint32_t)(kc % 3)*16384u;
            const uint32_t bBase = sb + SM_B + (uint32_t)(kc % 3)*16384u;
#pragma unroll
            for (int ks = 0; ks < 4; ks++) {
                uint32_t a[4][4];
#pragma unroll
                for (int mf = 0; mf < 4; mf++) {
                    uint32_t ad = aBase +
                        SW128(aRow + (uint32_t)mf*2048u + (uint32_t)ks*32u + aCol);
                    LDSM4(a[mf][0], a[mf][1], a[mf][2], a[mf][3], ad);
                }
                uint32_t bfr[4][2];
#pragma unroll
                for (int n2 = 0; n2 < 2; n2++) {
                    uint32_t bd = bBase +
                        SW128(bRow + (uint32_t)n2*2048u + (uint32_t)ks*32u + bCol);
                    uint32_t r0, r1, r2, r3;
                    LDSM4(r0, r1, r2, r3, bd);
                    bfr[n2*2][0] = r0;   bfr[n2*2][1] = r1;
                    bfr[n2*2+1][0] = r2; bfr[n2*2+1][1] = r3;
                }
#pragma unroll
                for (int mf = 0; mf < 4; mf++)
#pragma unroll
                    for (int nf = 0; nf < 4; nf++)
                        mma16816(c[mf][nf], a[mf], bfr[nf][0], bfr[nf][1]);
            }
        }

        // ---- epilogue for this 128-channel chunk
#pragma unroll
        for (int mf = 0; mf < 4; mf++)
#pragma unroll
            for (int nf = 0; nf < 4; nf++) {
                int nb = wn*32 + nf*8 + (lane & 3)*2;
                float q0 = qs[nb],   v0 = vs[nb];
                float q1 = qs[nb+1], v1 = vs[nb+1];
                rowsc[mf*2]   += fast_tanh(c[mf][nf][0] + q0)*v0
                               + fast_tanh(c[mf][nf][1] + q1)*v1;
                rowsc[mf*2+1] += fast_tanh(c[mf][nf][2] + q0)*v0
                               + fast_tanh(c[mf][nf][3] + q1)*v1;
            }
        __syncthreads();
    }

#pragma unroll
    for (int i = 0; i < 8; i++) {
        rowsc[i] += __shfl_xor_sync(~0u, rowsc[i], 1);
        rowsc[i] += __shfl_xor_sync(~0u, rowsc[i], 2);
    }
    if ((lane & 3) == 0) {
        int r = lane >> 2;
#pragma unroll
        for (int mf = 0; mf < 4; mf++) {
            part[wn*128 + wm*64 + mf*16 + r]     = rowsc[mf*2];
            part[wn*128 + wm*64 + mf*16 + r + 8] = rowsc[mf*2+1];
        }
    }
    __syncthreads();
    if (tid < 128) {
        float sfin = part[tid] + part[128+tid] + part[256+tid] + part[384+tid];
        g_scores[m0 + tid] = sfin;
        part[tid] = sfin;            // keep for stats (only [0,128) written)
    }
    __syncthreads();

    // ---- per-CTA softmax partial: warp 0 reduces the 128 scores in smem
    if (tid < 32) {
        float s0 = part[tid], s1 = part[tid+32], s2 = part[tid+64], s3 = part[tid+96];
        float m = fmaxf(fmaxf(s0, s1), fmaxf(s2, s3));
#pragma unroll
        for (int off = 16; off; off >>= 1) m = fmaxf(m, __shfl_xor_sync(~0u, m, off));
        float s = __expf(s0 - m) + __expf(s1 - m) + __expf(s2 - m) + __expf(s3 - m);
#pragma unroll
        for (int off = 16; off; off >>= 1) s += __shfl_xor_sync(~0u, s, off);
        if (tid == 0) g_pms[blockIdx.x] = make_float2(m, s);
    }
}

// ---------------------------------------------------------------------------
// fused alpha + context partials. 512 threads, 8-way s-split for deeper MLP.
// Prologue: combine this batch's 64 softmax partials -> (max, 1/sum).
// ---------------------------------------------------------------------------
__global__ __launch_bounds__(512)
void ctx_fused_kernel(float* __restrict__ alpha) {
    const int b = blockIdx.x, sc = blockIdx.y;   // 16 x 64
    const int t = threadIdx.x;                    // 512
    __shared__ float al[128];
    __shared__ float red[8*HH];                   // 16KB
    __shared__ float2 pms_sh[64];
    __shared__ float2 ms_sh;

    if (t < 64) pms_sh[t] = g_pms[b*64 + t];
    __syncthreads();
    if (t < 32) {
        float2 p0 = pms_sh[t], p1 = pms_sh[t+32];
        float m = fmaxf(p0.x, p1.x);
#pragma unroll
        for (int off = 16; off; off >>= 1) m = fmaxf(m, __shfl_xor_sync(~0u, m, off));
        float s = p0.y * __expf(p0.x - m) + p1.y * __expf(p1.x - m);
#pragma unroll
        for (int off = 16; off; off >>= 1) s += __shfl_xor_sync(~0u, s, off);
        if (t == 0) ms_sh = make_float2(m, 1.f / s);
    }
    __syncthreads();

    if (t < 128) {
        float2 ms = ms_sh;
        float a = __expf(g_scores[b*SS + sc*128 + t] - ms.x) * ms.y;
        al[t] = a;
        alpha[b*SS + sc*128 + t] = a;
    }
    __syncthreads();

    const int hg   = t & 63;          // h-group: 8 halfs = 1 uint4
    const int sway = t >> 6;          // 0..7 (16 rows each)
    const uint4* e = (const uint4*)(g_enc16 + ((size_t)b*SS + (size_t)sc*128)*HH);

    float acc[8];
#pragma unroll
    for (int j = 0; j < 8; j++) acc[j] = 0.f;

#pragma unroll 16
    for (int s = 0; s < 16; s++) {
        int row = sway*16 + s;
        float a = al[row];
        uint4 w = e[(size_t)row*(HH/8) + hg];
        float2 f0 = __half22float2(*(__half2*)&w.x);
        float2 f1 = __half22float2(*(__half2*)&w.y);
        float2 f2 = __half22float2(*(__half2*)&w.z);
        float2 f3 = __half22float2(*(__half2*)&w.w);
        acc[0] += a*f0.x; acc[1] += a*f0.y;
        acc[2] += a*f1.x; acc[3] += a*f1.y;
        acc[4] += a*f2.x; acc[5] += a*f2.y;
        acc[6] += a*f3.x; acc[7] += a*f3.y;
    }
#pragma unroll
    for (int j = 0; j < 8; j++) red[sway*HH + hg*8 + j] = acc[j];
    __syncthreads();

    // combine 8 s-ways; 512 threads cover 512 h
    {
        int h = t;
        float s = 0.f;
#pragma unroll
        for (int i = 0; i < 8; i++) s += red[i*HH + h];
        g_ctx_part[(size_t)(b*64 + sc)*HH + h] = s;
    }
}

// ---------------------------------------------------------------------------
// ctx_reduce: grid (16,4) x 128 thr
// ---------------------------------------------------------------------------
__global__ __launch_bounds__(128)
void ctx_reduce_kernel(float* __restrict__ ctx) {
    const int b = blockIdx.x;
    const int h = blockIdx.y * 128 + threadIdx.x;
    float s = 0.f;
#pragma unroll
    for (int i = 0; i < 64; i++)
        s += g_ctx_part[(size_t)(b*64 + i)*HH + h];
    ctx[b*HH + h] = s;
}

// ---------------------------------------------------------------------------
extern "C" void kernel_launch(void* const* d_in, const int* in_sizes, int n_in,
                              void* d_out, int out_size) {
    const float* enc   = (const float*)d_in[0];
    const float* query = (const float*)d_in[1];
    const float* Wh    = (const float*)d_in[2];
    const float* Wq    = (const float*)d_in[3];
    const float* v     = (const float*)d_in[4];

    float* ctx   = (float*)d_out;
    float* alpha = (float*)d_out + BB*HH;

    cudaFuncSetAttribute(scores_mma_kernel,
                         cudaFuncAttributeMaxDynamicSharedMemorySize, SM_TOTAL);

    prep_kernel<<<384, 256>>>(Wh, query, Wq);
    scores_mma_kernel<<<NROWS/128, 256, SM_TOTAL>>>(enc, v);
    ctx_fused_kernel<<<dim3(BB, 64), 512>>>(alpha);
    ctx_reduce_kernel<<<dim3(BB, 4), 128>>>(ctx);
}

// round 17
// speedup vs baseline: 1.0169x; 1.0169x over previous
#include <cuda_runtime.h>
#include <cuda_fp16.h>
#include <math.h>
#include <stdint.h>

#define BB 16
#define SS 8192
#define HH 512
#define NROWS (BB*SS)

// ---------------------------------------------------------------------------
// helpers
// ---------------------------------------------------------------------------
__device__ __forceinline__ uint32_t smem_u32(const void* p) {
    uint32_t a;
    asm("{ .reg .u64 t; cvta.to.shared.u64 t, %1; cvt.u32.u64 %0, t; }" : "=r"(a) : "l"(p));
    return a;
}
#define SW128(o) ((o) ^ (((o) >> 3) & 0x70))

#define LDSM4(r0,r1,r2,r3,addr)                                               \
    asm volatile("ldmatrix.sync.aligned.m8n8.x4.shared.b16 {%0,%1,%2,%3}, [%4];" \
        : "=r"(r0),"=r"(r1),"=r"(r2),"=r"(r3) : "r"(addr))

#define CP_ASYNC16(dst, src)                                                  \
    asm volatile("cp.async.ca.shared.global [%0], [%1], 16;" :: "r"(dst), "l"(src) : "memory")
#define CP_COMMIT()  asm volatile("cp.async.commit_group;" ::: "memory")
#define CP_WAIT1()   asm volatile("cp.async.wait_group 1;" ::: "memory")

__device__ __forceinline__ void mma16816(float* c, const uint32_t* a,
                                         uint32_t b0, uint32_t b1) {
    asm volatile(
        "mma.sync.aligned.m16n8k16.row.col.f32.f16.f16.f32 "
        "{%0,%1,%2,%3}, {%4,%5,%6,%7}, {%8,%9}, {%0,%1,%2,%3};"
        : "+f"(c[0]), "+f"(c[1]), "+f"(c[2]), "+f"(c[3])
        : "r"(a[0]), "r"(a[1]), "r"(a[2]), "r"(a[3]), "r"(b0), "r"(b1));
}

__device__ __forceinline__ float fast_tanh(float x) {
    float xc = fminf(x, 30.f);
    float e  = __expf(2.f * xc);
    return __fdividef(e - 1.f, e + 1.f);
}

// ---------------------------------------------------------------------------
// scratch
// ---------------------------------------------------------------------------
__device__ float  g_qproj[BB*HH];
__device__ float  g_scores[BB*SS];
__device__ float2 g_pms[NROWS/128];   // per-scores-CTA (max, sumexp)
__device__ float  g_ctx_part[BB*16*HH];
__device__ __align__(16) __half g_Wh16[HH*HH];              // W_h fp16, [o][k]
__device__ __align__(16) __half g_enc16[(size_t)NROWS*HH];  // enc fp16, [m][k]

// smem layout (bytes): 3-stage ring, each stage = A 16KB + B 16KB
#define SM_A     0                      // 3 stages x 128 rows x 128B = 48KB
#define SM_B     49152                  // 3 stages x 128 rows x 128B = 48KB
#define SM_Q     98304                  // 128 floats
#define SM_V     98816                  // 128 floats
#define SM_PART  99328                  // 4 x 128 floats
#define SM_TOTAL 101376

// ---------------------------------------------------------------------------
// prep: whcast (blocks 0..255) + qproj (blocks 256..511, 8 lanes/output)
// ---------------------------------------------------------------------------
__global__ __launch_bounds__(256)
void prep_kernel(const float* __restrict__ Wh,
                 const float* __restrict__ query,
                 const float* __restrict__ Wq) {
    const int bid = blockIdx.x;
    const int tid = threadIdx.x;
    if (bid < 256) {
        int i0 = (bid * 256 + tid) * 4;
        float4 x = *(const float4*)(Wh + i0);
        __half2 h01 = __float22half2_rn(make_float2(x.x, x.y));
        __half2 h23 = __float22half2_rn(make_float2(x.z, x.w));
        *(uint2*)(g_Wh16 + i0) = make_uint2(*(uint32_t*)&h01, *(uint32_t*)&h23);
    } else {
        // qproj: 256 blocks: b = bq>>4, og = bq&15 (32 outputs each, 8 lanes/o)
        const int bq = bid - 256;
        const int b  = bq >> 4;
        const int og = bq & 15;
        __shared__ float qs[HH];
        qs[tid] = query[b*HH + tid];
        qs[tid + 256] = query[b*HH + tid + 256];
        __syncthreads();

        const int o = og*32 + (tid >> 3);
        const int l = tid & 7;
        const float4* w4 = (const float4*)(Wq + (size_t)o*HH);
        const float4* q4 = (const float4*)qs;
        float acc = 0.f;
#pragma unroll
        for (int i = 0; i < 16; i++) {
            int k4 = l + 8*i;
            float4 w = w4[k4];
            float4 q = q4[k4];
            acc += w.x*q.x + w.y*q.y + w.z*q.z + w.w*q.w;
        }
        acc += __shfl_xor_sync(~0u, acc, 1);
        acc += __shfl_xor_sync(~0u, acc, 2);
        acc += __shfl_xor_sync(~0u, acc, 4);
        if (l == 0) g_qproj[b*HH + o] = acc;
    }
}

// ---------------------------------------------------------------------------
// convert one 64-k slice of A (128 rows) fp32 -> fp16: into swizzled smem slot
// AND to g_enc16 (for nc>=1 reuse and ctx). Same layout as the A cp.async.
// ---------------------------------------------------------------------------
__device__ __forceinline__ void conv_slice(char* smem, uint32_t slotBase,
                                           const float4* esrc, uint4* edst,
                                           int kn, int tid) {
#pragma unroll
    for (int i = 0; i < 4; i++) {
        int f = tid + i*256;
        int m = f >> 3, j = f & 7;
        const float4* s = esrc + (size_t)m*128 + kn*16 + j*2;
        float4 x0 = s[0];
        float4 x1 = s[1];
        __half2 a = __float22half2_rn(make_float2(x0.x, x0.y));
        __half2 b = __float22half2_rn(make_float2(x0.z, x0.w));
        __half2 c = __float22half2_rn(make_float2(x1.x, x1.y));
        __half2 d = __float22half2_rn(make_float2(x1.z, x1.w));
        uint4 o;
        o.x = *(uint32_t*)&a; o.y = *(uint32_t*)&b;
        o.z = *(uint32_t*)&c; o.w = *(uint32_t*)&d;
        *(uint4*)(smem + slotBase + SW128((uint32_t)(m*128 + j*16))) = o;
        edst[(size_t)m*64 + kn*8 + j] = o;
    }
}

// ---------------------------------------------------------------------------
// scores, single-pass fp16 mma, fully-async 3-stage pipeline (proven 250us).
// Tail: ONE WARP computes this CTA's softmax partial (max, sumexp) -> g_pms.
// ---------------------------------------------------------------------------
__global__ __launch_bounds__(256, 2)
void scores_mma_kernel(const float* __restrict__ encf,
                       const float* __restrict__ v) {
    extern __shared__ char smem[];
    const uint32_t sb = smem_u32(smem);
    const int tid  = threadIdx.x;
    const int lane = tid & 31;
    const int wid  = tid >> 5;
    const int wm   = wid & 1;          // 0..1  (64 rows each)
    const int wn   = wid >> 1;         // 0..3  (32 cols each)
    const int m0   = blockIdx.x * 128;
    const int b    = m0 / SS;

    float* qs   = (float*)(smem + SM_Q);
    float* vs   = (float*)(smem + SM_V);
    float* part = (float*)(smem + SM_PART);   // [4][128]

    const uint32_t aRow = (uint32_t)(wm*64 + (lane & 15)) * 128u;
    const uint32_t aCol = ((lane >> 4) & 1) * 16u;
    const uint32_t bRow = (uint32_t)(wn*32 + (lane & 7) + ((lane & 16) ? 8 : 0)) * 128u;
    const uint32_t bCol = ((lane & 8) ? 16u : 0u);

    const float4* esrc = (const float4*)(encf + (size_t)m0*HH);   // fp32 A
    uint4*        edst = (uint4*)(g_enc16 + (size_t)m0*HH);       // fp16 A out
    const uint4*  asrc = (const uint4*)(g_enc16 + (size_t)m0*HH); // fp16 A in
    const uint4*  wsrc = (const uint4*)g_Wh16;

    float rowsc[8];
#pragma unroll
    for (int i = 0; i < 8; i++) rowsc[i] = 0.f;

    for (int nc = 0; nc < 4; nc++) {
        if (tid < 128) {
            qs[tid] = g_qproj[b*HH + nc*128 + tid];
            vs[tid] = v[nc*128 + tid];
        }

        float c[4][4][4];
#pragma unroll
        for (int mf = 0; mf < 4; mf++)
#pragma unroll
            for (int nf = 0; nf < 4; nf++)
#pragma unroll
                for (int e = 0; e < 4; e++) c[mf][nf][e] = 0.f;

        // ---- prologue: stages for kc=0,1
#pragma unroll
        for (int pk = 0; pk < 2; pk++) {
            if (nc == 0) {
                conv_slice(smem, SM_A + (uint32_t)pk*16384u, esrc, edst, pk, tid);
            } else {
#pragma unroll
                for (int i = 0; i < 4; i++) {     // A stage pk via cp.async
                    int f = tid + i*256;
                    int m = f >> 3, j = f & 7;
                    uint32_t dst = sb + SM_A + (uint32_t)pk*16384u +
                                   SW128((uint32_t)(m*128 + j*16));
                    CP_ASYNC16(dst, asrc + (size_t)m*(HH/8) + pk*8 + j);
                }
            }
#pragma unroll
            for (int i = 0; i < 4; i++) {         // B stage pk
                int f = tid + i*256;
                int n = f >> 3, j = f & 7;
                uint32_t dst = sb + SM_B + (uint32_t)pk*16384u +
                               SW128((uint32_t)(n*128 + j*16));
                CP_ASYNC16(dst, wsrc + (size_t)(nc*128 + n)*(HH/8) + pk*8 + j);
            }
            CP_COMMIT();
        }
        if (nc == 0) __syncthreads();   // prologue STS visible before LDSM

        for (int kc = 0; kc < 8; kc++) {
            CP_WAIT1();
            __syncthreads();

            if (kc < 6) {
                const int kn = kc + 2;
                const uint32_t slot = (uint32_t)(kn % 3);
                if (nc == 0) {
                    conv_slice(smem, SM_A + slot*16384u, esrc, edst, kn, tid);
                } else {
#pragma unroll
                    for (int i = 0; i < 4; i++) {
                        int f = tid + i*256;
                        int m = f >> 3, j = f & 7;
                        uint32_t dst = sb + SM_A + slot*16384u +
                                       SW128((uint32_t)(m*128 + j*16));
                        CP_ASYNC16(dst, asrc + (size_t)m*(HH/8) + kn*8 + j);
                    }
                }
#pragma unroll
                for (int i = 0; i < 4; i++) {
                    int f = tid + i*256;
                    int n = f >> 3, j = f & 7;
                    uint32_t dst = sb + SM_B + slot*16384u +
                                   SW128((uint32_t)(n*128 + j*16));
                    CP_ASYNC16(dst, wsrc + (size_t)(nc*128 + n)*(HH/8) + kn*8 + j);
                }
            }
            CP_COMMIT();

            const uint32_t aBase = sb + SM_A + (uint32_t)(kc % 3)*16384u;
            const uint32_t bBase = sb + SM_B + (uint32_t)(kc % 3)*16384u;
#pragma unroll
            for (int ks = 0; ks < 4; ks++) {
                uint32_t a[4][4];
#pragma unroll
                for (int mf = 0; mf < 4; mf++) {
                    uint32_t ad = aBase +
                        SW128(aRow + (uint32_t)mf*2048u + (uint32_t)ks*32u + aCol);
                    LDSM4(a[mf][0], a[mf][1], a[mf][2], a[mf][3], ad);
                }
                uint32_t bfr[4][2];
#pragma unroll
                for (int n2 = 0; n2 < 2; n2++) {
                    uint32_t bd = bBase +
                        SW128(bRow + (uint32_t)n2*2048u + (uint32_t)ks*32u + bCol);
                    uint32_t r0, r1, r2, r3;
                    LDSM4(r0, r1, r2, r3, bd);
                    bfr[n2*2][0] = r0;   bfr[n2*2][1] = r1;
                    bfr[n2*2+1][0] = r2; bfr[n2*2+1][1] = r3;
                }
#pragma unroll
                for (int mf = 0; mf < 4; mf++)
#pragma unroll
                    for (int nf = 0; nf < 4; nf++)
                        mma16816(c[mf][nf], a[mf], bfr[nf][0], bfr[nf][1]);
            }
        }

        // ---- epilogue for this 128-channel chunk
#pragma unroll
        for (int mf = 0; mf < 4; mf++)
#pragma unroll
            for (int nf = 0; nf < 4; nf++) {
                int nb = wn*32 + nf*8 + (lane & 3)*2;
                float q0 = qs[nb],   v0 = vs[nb];
                float q1 = qs[nb+1], v1 = vs[nb+1];
                rowsc[mf*2]   += fast_tanh(c[mf][nf][0] + q0)*v0
                               + fast_tanh(c[mf][nf][1] + q1)*v1;
                rowsc[mf*2+1] += fast_tanh(c[mf][nf][2] + q0)*v0
                               + fast_tanh(c[mf][nf][3] + q1)*v1;
            }
        __syncthreads();
    }

#pragma unroll
    for (int i = 0; i < 8; i++) {
        rowsc[i] += __shfl_xor_sync(~0u, rowsc[i], 1);
        rowsc[i] += __shfl_xor_sync(~0u, rowsc[i], 2);
    }
    if ((lane & 3) == 0) {
        int r = lane >> 2;
#pragma unroll
        for (int mf = 0; mf < 4; mf++) {
            part[wn*128 + wm*64 + mf*16 + r]     = rowsc[mf*2];
            part[wn*128 + wm*64 + mf*16 + r + 8] = rowsc[mf*2+1];
        }
    }
    __syncthreads();
    if (tid < 128) {
        float sfin = part[tid] + part[128+tid] + part[256+tid] + part[384+tid];
        g_scores[m0 + tid] = sfin;
        part[tid] = sfin;            // keep for stats (only [0,128) written)
    }
    __syncthreads();

    // ---- per-CTA softmax partial: warp 0 reduces the 128 scores in smem
    if (tid < 32) {
        float s0 = part[tid], s1 = part[tid+32], s2 = part[tid+64], s3 = part[tid+96];
        float m = fmaxf(fmaxf(s0, s1), fmaxf(s2, s3));
#pragma unroll
        for (int off = 16; off; off >>= 1) m = fmaxf(m, __shfl_xor_sync(~0u, m, off));
        float s = __expf(s0 - m) + __expf(s1 - m) + __expf(s2 - m) + __expf(s3 - m);
#pragma unroll
        for (int off = 16; off; off >>= 1) s += __shfl_xor_sync(~0u, s, off);
        if (tid == 0) g_pms[blockIdx.x] = make_float2(m, s);
    }
}

// ---------------------------------------------------------------------------
// fused alpha + context partials: block (b, sc) covers 512 s-rows x 512 h.
// Grid (16, 16), 512 threads. Prologue combines the 64 softmax partials.
// ---------------------------------------------------------------------------
__global__ __launch_bounds__(512)
void ctx_fused_kernel(float* __restrict__ alpha) {
    const int b = blockIdx.x, sc = blockIdx.y;   // 16 x 16
    const int t = threadIdx.x;                    // 512
    __shared__ float al[512];
    __shared__ float red[8*HH];                   // 16KB
    __shared__ float2 pms_sh[64];
    __shared__ float2 ms_sh;

    if (t < 64) pms_sh[t] = g_pms[b*64 + t];
    __syncthreads();
    if (t < 32) {
        float2 p0 = pms_sh[t], p1 = pms_sh[t+32];
        float m = fmaxf(p0.x, p1.x);
#pragma unroll
        for (int off = 16; off; off >>= 1) m = fmaxf(m, __shfl_xor_sync(~0u, m, off));
        float s = p0.y * __expf(p0.x - m) + p1.y * __expf(p1.x - m);
#pragma unroll
        for (int off = 16; off; off >>= 1) s += __shfl_xor_sync(~0u, s, off);
        if (t == 0) ms_sh = make_float2(m, 1.f / s);
    }
    __syncthreads();

    {
        float2 ms = ms_sh;
        float a = __expf(g_scores[b*SS + sc*512 + t] - ms.x) * ms.y;
        al[t] = a;
        alpha[b*SS + sc*512 + t] = a;
    }
    __syncthreads();

    const int hg   = t & 63;          // h-group: 8 halfs = 1 uint4
    const int sway = t >> 6;          // 0..7 (64 rows each)
    const uint4* e = (const uint4*)(g_enc16 + ((size_t)b*SS + (size_t)sc*512)*HH);

    float acc[8];
#pragma unroll
    for (int j = 0; j < 8; j++) acc[j] = 0.f;

#pragma unroll 16
    for (int s = 0; s < 64; s++) {
        int row = sway*64 + s;
        float a = al[row];
        uint4 w = e[(size_t)row*(HH/8) + hg];
        float2 f0 = __half22float2(*(__half2*)&w.x);
        float2 f1 = __half22float2(*(__half2*)&w.y);
        float2 f2 = __half22float2(*(__half2*)&w.z);
        float2 f3 = __half22float2(*(__half2*)&w.w);
        acc[0] += a*f0.x; acc[1] += a*f0.y;
        acc[2] += a*f1.x; acc[3] += a*f1.y;
        acc[4] += a*f2.x; acc[5] += a*f2.y;
        acc[6] += a*f3.x; acc[7] += a*f3.y;
    }
#pragma unroll
    for (int j = 0; j < 8; j++) red[sway*HH + hg*8 + j] = acc[j];
    __syncthreads();

    // combine 8 s-ways; 512 threads cover 512 h
    {
        int h = t;
        float s = 0.f;
#pragma unroll
        for (int i = 0; i < 8; i++) s += red[i*HH + h];
        g_ctx_part[(size_t)(b*16 + sc)*HH + h] = s;
    }
}

// ---------------------------------------------------------------------------
// ctx_reduce: 16 partials per batch; grid (16,4) x 128 thr
// ---------------------------------------------------------------------------
__global__ __launch_bounds__(128)
void ctx_reduce_kernel(float* __restrict__ ctx) {
    const int b = blockIdx.x;
    const int h = blockIdx.y * 128 + threadIdx.x;
    float s = 0.f;
#pragma unroll
    for (int i = 0; i < 16; i++)
        s += g_ctx_part[(size_t)(b*16 + i)*HH + h];
    ctx[b*HH + h] = s;
}

// ---------------------------------------------------------------------------
extern "C" void kernel_launch(void* const* d_in, const int* in_sizes, int n_in,
                              void* d_out, int out_size) {
    const float* enc   = (const float*)d_in[0];
    const float* query = (const float*)d_in[1];
    const float* Wh    = (const float*)d_in[2];
    const float* Wq    = (const float*)d_in[3];
    const float* v     = (const float*)d_in[4];

    float* ctx   = (float*)d_out;
    float* alpha = (float*)d_out + BB*HH;

    cudaFuncSetAttribute(scores_mma_kernel,
                         cudaFuncAttributeMaxDynamicSharedMemorySize, SM_TOTAL);

    prep_kernel<<<512, 256>>>(Wh, query, Wq);
    scores_mma_kernel<<<NROWS/128, 256, SM_TOTAL>>>(enc, v);
    ctx_fused_kernel<<<dim3(BB, 16), 512>>>(alpha);
    ctx_reduce_kernel<<<dim3(BB, 4), 128>>>(ctx);
}